// round 2
// baseline (speedup 1.0000x reference)
#include <cuda_runtime.h>
#include <cuda_bf16.h>
#include <cstdint>
#include <cstddef>

#define B_SZ   32
#define LP     2048
#define LQ     512
#define DMODEL 256

#define N_X (B_SZ*LP*DMODEL)
#define N_Y (B_SZ*LQ*DMODEL)
#define N_W (DMODEL*DMODEL)
#define N_S ((size_t)B_SZ*LP*LQ)

__device__ unsigned char g_scratch[
    4ull*N_X + 4ull*N_Y + 4ull*N_W + 4ull*N_Y +   // x,y,w splits + yT split
    4ull*N_X + 4ull*N_Y +                          // xp, yp splits
    4ull*N_S + 4ull*N_S                            // S fp32, P split
];

__device__ __forceinline__ uint32_t s_u32(const void* p) {
    return (uint32_t)__cvta_generic_to_shared(p);
}
__device__ __forceinline__ void ldsm4(uint32_t* r, uint32_t a) {
    asm volatile("ldmatrix.sync.aligned.m8n8.x4.shared.b16 {%0,%1,%2,%3}, [%4];"
                 : "=r"(r[0]), "=r"(r[1]), "=r"(r[2]), "=r"(r[3]) : "r"(a));
}
__device__ __forceinline__ void ldsm2(uint32_t* r, uint32_t a) {
    asm volatile("ldmatrix.sync.aligned.m8n8.x2.shared.b16 {%0,%1}, [%2];"
                 : "=r"(r[0]), "=r"(r[1]) : "r"(a));
}
__device__ __forceinline__ void mma16816(float* c, const uint32_t* a, const uint32_t* b) {
    asm volatile("mma.sync.aligned.m16n8k16.row.col.f32.bf16.bf16.f32 "
                 "{%0,%1,%2,%3}, {%4,%5,%6,%7}, {%8,%9}, {%0,%1,%2,%3};"
                 : "+f"(c[0]), "+f"(c[1]), "+f"(c[2]), "+f"(c[3])
                 : "r"(a[0]), "r"(a[1]), "r"(a[2]), "r"(a[3]), "r"(b[0]), "r"(b[1]));
}
#define CPA16(s, g) asm volatile("cp.async.cg.shared.global [%0], [%1], 16;" :: "r"(s), "l"(g))

__device__ __forceinline__ void split_store2(__nv_bfloat16* __restrict__ H,
                                             __nv_bfloat16* __restrict__ L,
                                             size_t o, float v0, float v1) {
    __nv_bfloat16 h0 = __float2bfloat16(v0), h1 = __float2bfloat16(v1);
    float r0 = v0 - __bfloat162float(h0);
    float r1 = v1 - __bfloat162float(h1);
    *reinterpret_cast<__nv_bfloat162*>(H + o) = __halves2bfloat162(h0, h1);
    *reinterpret_cast<__nv_bfloat162*>(L + o) =
        __halves2bfloat162(__float2bfloat16(r0), __float2bfloat16(r1));
}

__global__ void split_kernel(const float* __restrict__ src,
                             __nv_bfloat16* __restrict__ hi,
                             __nv_bfloat16* __restrict__ lo, int n) {
    int i = blockIdx.x * blockDim.x + threadIdx.x;
    int stride = gridDim.x * blockDim.x;
    for (; i < n; i += stride) {
        float v = src[i];
        __nv_bfloat16 h = __float2bfloat16(v);
        hi[i] = h;
        lo[i] = __float2bfloat16(v - __bfloat162float(h));
    }
}

// y [B,LQ,D] -> yT hi/lo [B,D,LQ]
__global__ void transpose_split_kernel(const float* __restrict__ y,
                                       __nv_bfloat16* __restrict__ th,
                                       __nv_bfloat16* __restrict__ tl) {
    __shared__ float tile[32][33];
    int b = blockIdx.z, q0 = blockIdx.y * 32, d0 = blockIdx.x * 32;
    int tx = threadIdx.x & 31, ty = threadIdx.x >> 5;
    const float* yb = y + ((size_t)b * LQ + q0) * DMODEL + d0;
#pragma unroll
    for (int j = 0; j < 32; j += 8)
        tile[ty + j][tx] = yb[(size_t)(ty + j) * DMODEL + tx];
    __syncthreads();
    __nv_bfloat16* thb = th + ((size_t)b * DMODEL + d0) * LQ + q0;
    __nv_bfloat16* tlb = tl + ((size_t)b * DMODEL + d0) * LQ + q0;
#pragma unroll
    for (int j = 0; j < 32; j += 8) {
        float v = tile[tx][ty + j];
        __nv_bfloat16 h = __float2bfloat16(v);
        thb[(size_t)(ty + j) * LQ + tx] = h;
        tlb[(size_t)(ty + j) * LQ + tx] = __float2bfloat16(v - __bfloat162float(h));
    }
}

// C[M,N] = A[M,KT] @ B[N,KT]^T, split-bf16 (hh+hl+lh), 128x128 tile, 8 warps.
#define TM  128
#define TN  128
#define KC  16
#define SLD 24
#define TSZ (TM*SLD)

template<int KT, bool RELU_SPLIT>
__global__ void __launch_bounds__(256) gemm_split_kernel(
    const __nv_bfloat16* __restrict__ Ah, const __nv_bfloat16* __restrict__ Al,
    const __nv_bfloat16* __restrict__ Bh, const __nv_bfloat16* __restrict__ Bl,
    float* __restrict__ Cf,
    __nv_bfloat16* __restrict__ Ch, __nv_bfloat16* __restrict__ Cl,
    const float* __restrict__ bias, int N,
    long long sA, long long sB, long long sC)
{
    __shared__ __align__(16) __nv_bfloat16 sAh[2*TSZ], sAl[2*TSZ], sBh[2*TSZ], sBl[2*TSZ];

    const int tid = threadIdx.x;
    const int bz = blockIdx.z;
    const int m0 = blockIdx.y * TM, n0 = blockIdx.x * TN;

    const int lrow = tid >> 1, lhalf = (tid & 1) * 8;
    const __nv_bfloat16* pAh = Ah + (long long)bz * sA + (size_t)(m0 + lrow) * KT + lhalf;
    const __nv_bfloat16* pAl = Al + (long long)bz * sA + (size_t)(m0 + lrow) * KT + lhalf;
    const __nv_bfloat16* pBh = Bh + (long long)bz * sB + (size_t)(n0 + lrow) * KT + lhalf;
    const __nv_bfloat16* pBl = Bl + (long long)bz * sB + (size_t)(n0 + lrow) * KT + lhalf;
    const int soff = lrow * SLD + lhalf;

#define LOAD_CHUNK(c, buf) do {                                   \
        int _s = (buf) * TSZ + soff; int _ko = (c) * KC;          \
        CPA16(s_u32(sAh + _s), pAh + _ko);                        \
        CPA16(s_u32(sAl + _s), pAl + _ko);                        \
        CPA16(s_u32(sBh + _s), pBh + _ko);                        \
        CPA16(s_u32(sBl + _s), pBl + _ko);                        \
        asm volatile("cp.async.commit_group;" ::: "memory");      \
    } while (0)

    const int lane = tid & 31, warp = tid >> 5;
    const int wr = warp >> 2, wc = warp & 3;
    const int g = lane >> 2, t4 = lane & 3;
    const int aRow = wr * 64 + (lane & 15);
    const int aCol = ((lane >> 4) << 3);
    const int bRow = wc * 32 + (lane & 7);
    const int bCol = (((lane >> 3) & 1) << 3);

    float acc[4][4][4];
#pragma unroll
    for (int m = 0; m < 4; ++m)
#pragma unroll
        for (int n = 0; n < 4; ++n)
#pragma unroll
            for (int k = 0; k < 4; ++k) acc[m][n][k] = 0.0f;

    constexpr int NC = KT / KC;
    LOAD_CHUNK(0, 0);
#pragma unroll 1
    for (int c = 0; c < NC; ++c) {
        if (c + 1 < NC) {
            LOAD_CHUNK(c + 1, (c + 1) & 1);
            asm volatile("cp.async.wait_group 1;" ::: "memory");
        } else {
            asm volatile("cp.async.wait_group 0;" ::: "memory");
        }
        __syncthreads();
        const int off = (c & 1) * TSZ;

        uint32_t ah[4][4], al[4][4], bh[4][2], bl[4][2];
#pragma unroll
        for (int m = 0; m < 4; ++m) {
            ldsm4(ah[m], s_u32(sAh + off + (aRow + m * 16) * SLD + aCol));
            ldsm4(al[m], s_u32(sAl + off + (aRow + m * 16) * SLD + aCol));
        }
#pragma unroll
        for (int n = 0; n < 4; ++n) {
            ldsm2(bh[n], s_u32(sBh + off + (bRow + n * 8) * SLD + bCol));
            ldsm2(bl[n], s_u32(sBl + off + (bRow + n * 8) * SLD + bCol));
        }
#pragma unroll
        for (int m = 0; m < 4; ++m)
#pragma unroll
            for (int n = 0; n < 4; ++n) {
                mma16816(acc[m][n], ah[m], bh[n]);
                mma16816(acc[m][n], ah[m], bl[n]);
                mma16816(acc[m][n], al[m], bh[n]);
            }
        __syncthreads();
    }
#undef LOAD_CHUNK

    const size_t cBase = (size_t)((long long)bz * sC);
#pragma unroll
    for (int m = 0; m < 4; ++m) {
#pragma unroll
        for (int n = 0; n < 4; ++n) {
            int r0 = m0 + wr * 64 + m * 16 + g;
            int c0 = n0 + wc * 32 + n * 8 + 2 * t4;
            size_t o0 = cBase + (size_t)r0 * N + c0;
            size_t o1 = o0 + (size_t)8 * N;
            float a0 = acc[m][n][0], a1 = acc[m][n][1];
            float a2 = acc[m][n][2], a3 = acc[m][n][3];
            if constexpr (RELU_SPLIT) {
                float b0 = __ldg(bias + c0), b1 = __ldg(bias + c0 + 1);
                a0 = fmaxf(a0 + b0, 0.0f); a1 = fmaxf(a1 + b1, 0.0f);
                a2 = fmaxf(a2 + b0, 0.0f); a3 = fmaxf(a3 + b1, 0.0f);
                split_store2(Ch, Cl, o0, a0, a1);
                split_store2(Ch, Cl, o1, a2, a3);
            } else {
                *reinterpret_cast<float2*>(Cf + o0) = make_float2(a0, a1);
                *reinterpret_cast<float2*>(Cf + o1) = make_float2(a2, a3);
            }
        }
    }
}

// row softmax over 512 cols -> P hi/lo bf16; one warp per row
__global__ void softmax_split_kernel(const float* __restrict__ S,
                                     __nv_bfloat16* __restrict__ Ph,
                                     __nv_bfloat16* __restrict__ Pl) {
    int row = blockIdx.x * 8 + (threadIdx.x >> 5);
    int lane = threadIdx.x & 31;
    const float* r = S + (size_t)row * LQ;
    float v[16];
#pragma unroll
    for (int i = 0; i < 16; ++i) v[i] = r[i * 32 + lane];
    float m = v[0];
#pragma unroll
    for (int i = 1; i < 16; ++i) m = fmaxf(m, v[i]);
#pragma unroll
    for (int o = 16; o > 0; o >>= 1) m = fmaxf(m, __shfl_xor_sync(0xffffffffu, m, o));
    float s = 0.0f;
#pragma unroll
    for (int i = 0; i < 16; ++i) { v[i] = __expf(v[i] - m); s += v[i]; }
#pragma unroll
    for (int o = 16; o > 0; o >>= 1) s += __shfl_xor_sync(0xffffffffu, s, o);
    float inv = 1.0f / s;
#pragma unroll
    for (int i = 0; i < 16; ++i) {
        float p = v[i] * inv;
        __nv_bfloat16 h = __float2bfloat16(p);
        size_t o = (size_t)row * LQ + i * 32 + lane;
        Ph[o] = h;
        Pl[o] = __float2bfloat16(p - __bfloat162float(h));
    }
}

extern "C" void kernel_launch(void* const* d_in, const int* in_sizes, int n_in,
                              void* d_out, int out_size)
{
    const float *x = nullptr, *y = nullptr, *W = nullptr, *bias = nullptr;
    for (int i = 0; i < n_in; ++i) {
        switch (in_sizes[i]) {
            case N_X:    x    = (const float*)d_in[i]; break;
            case N_Y:    y    = (const float*)d_in[i]; break;
            case N_W:    W    = (const float*)d_in[i]; break;
            case DMODEL: bias = (const float*)d_in[i]; break;
            default: break;
        }
    }
    float* out = (float*)d_out;

    void* base = nullptr;
    cudaGetSymbolAddress(&base, g_scratch);
    unsigned char* p = (unsigned char*)base;
    __nv_bfloat16* x_hi  = (__nv_bfloat16*)p; p += 2ull*N_X;
    __nv_bfloat16* x_lo  = (__nv_bfloat16*)p; p += 2ull*N_X;
    __nv_bfloat16* y_hi  = (__nv_bfloat16*)p; p += 2ull*N_Y;
    __nv_bfloat16* y_lo  = (__nv_bfloat16*)p; p += 2ull*N_Y;
    __nv_bfloat16* w_hi  = (__nv_bfloat16*)p; p += 2ull*N_W;
    __nv_bfloat16* w_lo  = (__nv_bfloat16*)p; p += 2ull*N_W;
    __nv_bfloat16* yT_hi = (__nv_bfloat16*)p; p += 2ull*N_Y;
    __nv_bfloat16* yT_lo = (__nv_bfloat16*)p; p += 2ull*N_Y;
    __nv_bfloat16* xp_hi = (__nv_bfloat16*)p; p += 2ull*N_X;
    __nv_bfloat16* xp_lo = (__nv_bfloat16*)p; p += 2ull*N_X;
    __nv_bfloat16* yp_hi = (__nv_bfloat16*)p; p += 2ull*N_Y;
    __nv_bfloat16* yp_lo = (__nv_bfloat16*)p; p += 2ull*N_Y;
    float*         S     = (float*)p;         p += 4ull*N_S;
    __nv_bfloat16* P_hi  = (__nv_bfloat16*)p; p += 2ull*N_S;
    __nv_bfloat16* P_lo  = (__nv_bfloat16*)p; p += 2ull*N_S;

    split_kernel<<<4096, 256>>>(x, x_hi, x_lo, N_X);
    split_kernel<<<2048, 256>>>(y, y_hi, y_lo, N_Y);
    split_kernel<<<256,  256>>>(W, w_hi, w_lo, N_W);
    transpose_split_kernel<<<dim3(DMODEL/32, LQ/32, B_SZ), 256>>>(y, yT_hi, yT_lo);

    // xp = relu(x@W^T+b), yp = relu(y@W^T+b)  (M = B*LP / B*LQ flattened, z=1)
    gemm_split_kernel<256, true><<<dim3(DMODEL/TN, (B_SZ*LP)/TM, 1), 256>>>(
        x_hi, x_lo, w_hi, w_lo, nullptr, xp_hi, xp_lo, bias, DMODEL, 0, 0, 0);
    gemm_split_kernel<256, true><<<dim3(DMODEL/TN, (B_SZ*LQ)/TM, 1), 256>>>(
        y_hi, y_lo, w_hi, w_lo, nullptr, yp_hi, yp_lo, bias, DMODEL, 0, 0, 0);

    // S[b] = xp[b] @ yp[b]^T   [LP, LQ]
    gemm_split_kernel<256, false><<<dim3(LQ/TN, LP/TM, B_SZ), 256>>>(
        xp_hi, xp_lo, yp_hi, yp_lo, S, nullptr, nullptr, nullptr, LQ,
        (long long)LP*DMODEL, (long long)LQ*DMODEL, (long long)LP*LQ);

    // softmax rows of S -> P hi/lo
    softmax_split_kernel<<<(B_SZ*LP)/8, 256>>>(S, P_hi, P_lo);

    // out[b] = P[b] @ yT[b]^T   [LP, D]  (yT is [D, LQ], k-contiguous over LQ)
    gemm_split_kernel<512, false><<<dim3(DMODEL/TN, LP/TM, B_SZ), 256>>>(
        P_hi, P_lo, yT_hi, yT_lo, out, nullptr, nullptr, nullptr, DMODEL,
        (long long)LP*LQ, (long long)DMODEL*LQ, (long long)LP*DMODEL);
}